// round 12
// baseline (speedup 1.0000x reference)
#include <cuda_runtime.h>
#include <cuda_bf16.h>

#define BB 8
#define NN 2048
#define BIGF 1e30f

// chamfer shape: cnt-relative chunks (zero dead blocks) + QPT amortization
#define TB     128
#define QPT    4
#define QSTEP  (QPT * TB)        // 512 query slots per pass
#define GQ     2                 // query chunks
#define RSPLIT 64                // ref chunks
#define RTILE  32                // max rlen = ceil(2048/64)
#define GZ     (2 * BB)          // 16 tasks
#define ARR_PER_TASK (GQ * RSPLIT)   // 128 arrivals per task

// Scratch (allocation-free). Points transformed: (x+y, x-y, z, 0).
// g_valid[0]=clean(points+target), g_valid[1]=predp(points+pred)
__device__ __align__(16) float4       g_valid[2][BB][NN];
__device__ __align__(16) unsigned int g_minbits[2][BB][NN];
__device__ int          g_cnt[BB];          // zero at load; reset by last block
__device__ float        g_l1part[128];
__device__ float        g_tasksum[GZ];
__device__ unsigned int g_done_task[GZ];
__device__ unsigned int g_done;

// ---------------------------------------------------------------------------
// Kernel 1: prep — 128 blocks x 128 threads, one point per thread.
// ---------------------------------------------------------------------------
__global__ void __launch_bounds__(128)
prep_kernel(const float* __restrict__ pred,
            const float* __restrict__ target,
            const int*   __restrict__ mask,
            const float* __restrict__ points) {
    int bid = blockIdx.x, tid = threadIdx.x;
    int b = bid >> 4, s = bid & 15;
    int n  = s * 128 + tid;
    int gi = b * NN + n;

    const float* pp = pred   + gi * 3;
    const float* tt = target + gi * 3;
    const float* xx = points + gi * 3;
    float p0 = pp[0], p1 = pp[1], p2 = pp[2];
    float t0 = tt[0], t1 = tt[1], t2 = tt[2];
    float x0 = xx[0], x1 = xx[1], x2 = xx[2];
    int m = mask[gi];

    const unsigned bigbits = __float_as_uint(BIGF);
    g_minbits[0][b][n] = bigbits;
    g_minbits[1][b][n] = bigbits;

    float c0 = x0 + t0, c1 = x1 + t1, c2 = x2 + t2;   // clean
    float q0 = x0 + p0, q1 = x1 + p1, q2 = x2 + p2;   // predp
    float l1 = 0.f;

    __shared__ int sh_cnt, sh_base;
    if (tid == 0) sh_cnt = 0;
    __syncthreads();
    int klocal = -1;
    if (m) {
        l1 = fabsf(p0 - t0) + fabsf(p1 - t1) + fabsf(p2 - t2);
        klocal = atomicAdd(&sh_cnt, 1);
    }
    __syncthreads();
    if (tid == 0) sh_base = atomicAdd(&g_cnt[b], sh_cnt);

    __shared__ float wsum[4];
#pragma unroll
    for (int o = 16; o > 0; o >>= 1) l1 += __shfl_down_sync(0xffffffffu, l1, o);
    if ((tid & 31) == 0) wsum[tid >> 5] = l1;
    __syncthreads();
    if (tid == 0)
        g_l1part[bid] = wsum[0] + wsum[1] + wsum[2] + wsum[3];

    if (m) {
        int k = sh_base + klocal;
        g_valid[0][b][k] = make_float4(c0 + c1, c0 - c1, c2, 0.f);
        g_valid[1][b][k] = make_float4(q0 + q1, q0 - q1, q2, 0.f);
    }
}

// ---------------------------------------------------------------------------
// Kernel 2: chamfer, grid (GQ, RSPLIT, GZ) = (2, 64, 16) = 2048 blocks, TB=128.
// cnt-relative q and r chunks; 4 register queries share each tile load.
// |dx|+|dy|+|dz| == max(|du|,|dv|) + |dz| with (u,v) = (x+y, x-y).
// ---------------------------------------------------------------------------
__global__ void __launch_bounds__(TB)
chamfer_kernel(float* __restrict__ out) {
    int tid  = threadIdx.x;
    int task = blockIdx.z;
    int b    = task >> 1;
    int dir  = task & 1;               // 0: clean->pred, 1: pred->clean
    int cnt  = g_cnt[b];

    __shared__ float4 tile[RTILE];
    int qn   = (cnt + GQ - 1) / GQ;            // <= 1024
    int q_lo = blockIdx.x * qn;
    int q_hi = min(q_lo + qn, cnt);
    int rn   = (cnt + RSPLIT - 1) / RSPLIT;    // <= 32
    int r_lo = blockIdx.y * rn;
    int rlen = min(rn, cnt - r_lo);

    if (q_lo < cnt && rlen > 0) {
        const float4* __restrict__ Q = g_valid[dir][b];
        const float4* __restrict__ R = g_valid[dir ^ 1][b];
        unsigned int* __restrict__ M = g_minbits[dir][b];

        if (tid < RTILE)
            tile[tid] = (tid < rlen) ? R[r_lo + tid]
                                     : make_float4(BIGF, BIGF, BIGF, 0.f);
        __syncthreads();

        for (int q0 = q_lo; q0 < q_hi; q0 += QSTEP) {   // 1 pass @ cnt<=1024
            int qi0 = q0 + tid;
            int qi1 = qi0 + TB;
            int qi2 = qi0 + 2 * TB;
            int qi3 = qi0 + 3 * TB;
            float4 v0 = Q[min(qi0, NN - 1)];
            float4 v1 = Q[min(qi1, NN - 1)];
            float4 v2 = Q[min(qi2, NN - 1)];
            float4 v3 = Q[min(qi3, NN - 1)];
            float qx0 = v0.x, qy0 = v0.y, qz0 = v0.z;
            float qx1 = v1.x, qy1 = v1.y, qz1 = v1.z;
            float qx2 = v2.x, qy2 = v2.y, qz2 = v2.z;
            float qx3 = v3.x, qy3 = v3.y, qz3 = v3.z;
            float mn0 = BIGF, mn1 = BIGF, mn2 = BIGF, mn3 = BIGF;

#pragma unroll 4
            for (int j = 0; j < rlen; ++j) {
                float4 y = tile[j];            // uniform LDS.128 broadcast
                float d0 = fmaxf(fabsf(qx0 - y.x), fabsf(qy0 - y.y)) + fabsf(qz0 - y.z);
                mn0 = fminf(mn0, d0);
                float d1 = fmaxf(fabsf(qx1 - y.x), fabsf(qy1 - y.y)) + fabsf(qz1 - y.z);
                mn1 = fminf(mn1, d1);
                float d2 = fmaxf(fabsf(qx2 - y.x), fabsf(qy2 - y.y)) + fabsf(qz2 - y.z);
                mn2 = fminf(mn2, d2);
                float d3 = fmaxf(fabsf(qx3 - y.x), fabsf(qy3 - y.y)) + fabsf(qz3 - y.z);
                mn3 = fminf(mn3, d3);
            }

            if (qi0 < q_hi) atomicMin(&M[qi0], __float_as_uint(mn0));
            if (qi1 < q_hi) atomicMin(&M[qi1], __float_as_uint(mn1));
            if (qi2 < q_hi) atomicMin(&M[qi2], __float_as_uint(mn2));
            if (qi3 < q_hi) atomicMin(&M[qi3], __float_as_uint(mn3));
        }
    }

    // -------- hierarchical arrive --------
    __threadfence();
    __syncthreads();
    __shared__ int task_last;
    if (tid == 0)
        task_last = (atomicAdd(&g_done_task[task], 1u) == ARR_PER_TASK - 1);
    __syncthreads();
    if (!task_last) return;

    // -------- per-task tail: reduce this (dir,b) min array to one scalar ----
    __threadfence();
    {
        const uint4* __restrict__ p = (const uint4*)g_minbits[dir][b];
        int nv = cnt >> 2;
        float s = 0.f;
        for (int k = tid; k < nv; k += TB) {
            uint4 u = p[k];
            s += (__uint_as_float(u.x) + __uint_as_float(u.y))
               + (__uint_as_float(u.z) + __uint_as_float(u.w));
        }
        if (tid < (cnt & 3))
            s += __uint_as_float(g_minbits[dir][b][(cnt & ~3) + tid]);

        __shared__ float wsum[4];
#pragma unroll
        for (int o = 16; o > 0; o >>= 1) s += __shfl_down_sync(0xffffffffu, s, o);
        if ((tid & 31) == 0) wsum[tid >> 5] = s;
        __syncthreads();
        if (tid == 0)
            g_tasksum[task] = wsum[0] + wsum[1] + wsum[2] + wsum[3];
    }

    // -------- global arrive; last task-block combines --------
    __threadfence();
    __syncthreads();
    __shared__ int is_last;
    if (tid == 0)
        is_last = (atomicAdd(&g_done, 1u) == GZ - 1);
    __syncthreads();
    if (!is_last) return;

    __threadfence();
    float l1p = g_l1part[tid];             // 128 partials, TB == 128
    __shared__ float wl[4];
#pragma unroll
    for (int o = 16; o > 0; o >>= 1) l1p += __shfl_down_sync(0xffffffffu, l1p, o);
    if ((tid & 31) == 0) wl[tid >> 5] = l1p;
    __syncthreads();
    if (tid == 0) {
        float cdsum = 0.f;
#pragma unroll
        for (int t = 0; t < GZ; ++t)
            cdsum += g_tasksum[t] / (float)g_cnt[t >> 1];
        float l1num = wl[0] + wl[1] + wl[2] + wl[3];
        int msum = 0;
#pragma unroll
        for (int bb = 0; bb < BB; ++bb) msum += g_cnt[bb];
        float l1 = l1num / 3.0f / (float)msum;
        float cd = cdsum / (float)BB;
        out[0] = l1 + expf(-l1) * cd;
        g_done = 0;                        // reset for next graph replay
    }
    __syncthreads();
    if (tid < BB)  g_cnt[tid] = 0;
    if (tid < GZ)  g_done_task[tid] = 0;
}

// ---------------------------------------------------------------------------
extern "C" void kernel_launch(void* const* d_in, const int* in_sizes, int n_in,
                              void* d_out, int out_size) {
    const float* pred   = (const float*)d_in[0];
    const float* target = (const float*)d_in[1];
    const int*   mask   = (const int*)  d_in[2];
    const float* points = (const float*)d_in[3];
    float* out = (float*)d_out;

    prep_kernel<<<128, 128>>>(pred, target, mask, points);

    dim3 grid(GQ, RSPLIT, GZ);   // (2, 64, 16) = 2048 blocks, all live
    chamfer_kernel<<<grid, TB>>>(out);
}

// round 13
// speedup vs baseline: 1.0538x; 1.0538x over previous
#include <cuda_runtime.h>
#include <cuda_bf16.h>

#define BB 8
#define NN 2048
#define NPAD (NN + 512)
#define BIGF 1e30f

// chamfer shape: R11 geometry + QPT=2 tile amortization
#define TB     128
#define QPT    2
#define QSTEP  (QPT * TB)        // 256 query slots per pass
#define GQ     4                 // query chunks (qn ~ 256 -> one pass typ.)
#define RSPLIT 32                // ref chunks (rlen ~ 32)
#define RTILE  64                // max rlen = ceil(2048/32)
#define GZ     (2 * BB)          // 16 tasks
#define ARR_PER_TASK (GQ * RSPLIT)   // 128 arrivals per task

// Scratch (allocation-free). Points transformed: (x+y, x-y, z, 0).
// g_valid[0]=clean(points+target), g_valid[1]=predp(points+pred)
// Padded so query loads need no clamping (pad region never stored/used).
__device__ __align__(16) float4       g_valid[2][BB][NPAD];
__device__ __align__(16) unsigned int g_minbits[2][BB][NN];
__device__ int          g_cnt[BB];          // zero at load; reset by last block
__device__ float        g_l1part[128];
__device__ float        g_tasksum[GZ];
__device__ unsigned int g_done_task[GZ];
__device__ unsigned int g_done;

// ---------------------------------------------------------------------------
// Kernel 1: prep — 128 blocks x 128 threads, one point per thread.
// ---------------------------------------------------------------------------
__global__ void __launch_bounds__(128)
prep_kernel(const float* __restrict__ pred,
            const float* __restrict__ target,
            const int*   __restrict__ mask,
            const float* __restrict__ points) {
    int bid = blockIdx.x, tid = threadIdx.x;
    int b = bid >> 4, s = bid & 15;
    int n  = s * 128 + tid;
    int gi = b * NN + n;

    const float* pp = pred   + gi * 3;
    const float* tt = target + gi * 3;
    const float* xx = points + gi * 3;
    float p0 = pp[0], p1 = pp[1], p2 = pp[2];
    float t0 = tt[0], t1 = tt[1], t2 = tt[2];
    float x0 = xx[0], x1 = xx[1], x2 = xx[2];
    int m = mask[gi];

    const unsigned bigbits = __float_as_uint(BIGF);
    g_minbits[0][b][n] = bigbits;
    g_minbits[1][b][n] = bigbits;

    float c0 = x0 + t0, c1 = x1 + t1, c2 = x2 + t2;   // clean
    float q0 = x0 + p0, q1 = x1 + p1, q2 = x2 + p2;   // predp
    float l1 = 0.f;

    __shared__ int sh_cnt, sh_base;
    if (tid == 0) sh_cnt = 0;
    __syncthreads();
    int klocal = -1;
    if (m) {
        l1 = fabsf(p0 - t0) + fabsf(p1 - t1) + fabsf(p2 - t2);
        klocal = atomicAdd(&sh_cnt, 1);
    }
    __syncthreads();
    if (tid == 0) sh_base = atomicAdd(&g_cnt[b], sh_cnt);

    __shared__ float wsum[4];
#pragma unroll
    for (int o = 16; o > 0; o >>= 1) l1 += __shfl_down_sync(0xffffffffu, l1, o);
    if ((tid & 31) == 0) wsum[tid >> 5] = l1;
    __syncthreads();
    if (tid == 0)
        g_l1part[bid] = wsum[0] + wsum[1] + wsum[2] + wsum[3];

    if (m) {
        int k = sh_base + klocal;
        g_valid[0][b][k] = make_float4(c0 + c1, c0 - c1, c2, 0.f);
        g_valid[1][b][k] = make_float4(q0 + q1, q0 - q1, q2, 0.f);
    }
}

// ---------------------------------------------------------------------------
// Kernel 2: chamfer, grid (GQ, RSPLIT, GZ) = (4, 32, 16) = 2048 blocks, TB=128.
// cnt-relative q and r chunks; 2 register queries share each tile load.
// |dx|+|dy|+|dz| == max(|du|,|dv|) + |dz| with (u,v) = (x+y, x-y).
// ---------------------------------------------------------------------------
__global__ void __launch_bounds__(TB)
chamfer_kernel(float* __restrict__ out) {
    int tid  = threadIdx.x;
    int task = blockIdx.z;
    int b    = task >> 1;
    int dir  = task & 1;               // 0: clean->pred, 1: pred->clean
    int cnt  = g_cnt[b];

    __shared__ float4 tile[RTILE];
    int qn   = (cnt + GQ - 1) / GQ;            // ~256
    int q_lo = blockIdx.x * qn;
    int q_hi = min(q_lo + qn, cnt);
    int rn   = (cnt + RSPLIT - 1) / RSPLIT;    // <= 64
    int r_lo = blockIdx.y * rn;
    int rlen = min(rn, cnt - r_lo);

    if (q_lo < cnt && rlen > 0) {
        const float4* __restrict__ Q = g_valid[dir][b];
        const float4* __restrict__ R = g_valid[dir ^ 1][b];
        unsigned int* __restrict__ M = g_minbits[dir][b];

        if (tid < RTILE)
            tile[tid] = (tid < rlen) ? R[r_lo + tid]
                                     : make_float4(BIGF, BIGF, BIGF, 0.f);
        __syncthreads();

        for (int q0 = q_lo; q0 < q_hi; q0 += QSTEP) {   // 1 pass typical
            int qi0 = q0 + tid;            // unguarded: g_valid padded past NN
            int qi1 = qi0 + TB;
            float4 v0 = Q[qi0];
            float4 v1 = Q[qi1];
            float qx0 = v0.x, qy0 = v0.y, qz0 = v0.z;
            float qx1 = v1.x, qy1 = v1.y, qz1 = v1.z;
            float mn0 = BIGF, mn1 = BIGF;

#pragma unroll 8
            for (int j = 0; j < rlen; ++j) {
                float4 y = tile[j];        // uniform LDS.128 broadcast
                float d0 = fmaxf(fabsf(qx0 - y.x), fabsf(qy0 - y.y)) + fabsf(qz0 - y.z);
                mn0 = fminf(mn0, d0);
                float d1 = fmaxf(fabsf(qx1 - y.x), fabsf(qy1 - y.y)) + fabsf(qz1 - y.z);
                mn1 = fminf(mn1, d1);
            }

            if (qi0 < q_hi) atomicMin(&M[qi0], __float_as_uint(mn0));
            if (qi1 < q_hi) atomicMin(&M[qi1], __float_as_uint(mn1));
        }
    }

    // -------- hierarchical arrive --------
    __threadfence();
    __syncthreads();
    __shared__ int task_last;
    if (tid == 0)
        task_last = (atomicAdd(&g_done_task[task], 1u) == ARR_PER_TASK - 1);
    __syncthreads();
    if (!task_last) return;

    // -------- per-task tail: reduce this (dir,b) min array to one scalar ----
    __threadfence();
    {
        const uint4* __restrict__ p = (const uint4*)g_minbits[dir][b];
        int nv = cnt >> 2;
        float s = 0.f;
        for (int k = tid; k < nv; k += TB) {
            uint4 u = p[k];
            s += (__uint_as_float(u.x) + __uint_as_float(u.y))
               + (__uint_as_float(u.z) + __uint_as_float(u.w));
        }
        if (tid < (cnt & 3))
            s += __uint_as_float(g_minbits[dir][b][(cnt & ~3) + tid]);

        __shared__ float wsum[4];
#pragma unroll
        for (int o = 16; o > 0; o >>= 1) s += __shfl_down_sync(0xffffffffu, s, o);
        if ((tid & 31) == 0) wsum[tid >> 5] = s;
        __syncthreads();
        if (tid == 0)
            g_tasksum[task] = wsum[0] + wsum[1] + wsum[2] + wsum[3];
    }

    // -------- global arrive; last task-block combines --------
    __threadfence();
    __syncthreads();
    __shared__ int is_last;
    if (tid == 0)
        is_last = (atomicAdd(&g_done, 1u) == GZ - 1);
    __syncthreads();
    if (!is_last) return;

    __threadfence();
    float l1p = g_l1part[tid];             // 128 partials, TB == 128
    __shared__ float wl[4];
#pragma unroll
    for (int o = 16; o > 0; o >>= 1) l1p += __shfl_down_sync(0xffffffffu, l1p, o);
    if ((tid & 31) == 0) wl[tid >> 5] = l1p;
    __syncthreads();
    if (tid == 0) {
        float cdsum = 0.f;
#pragma unroll
        for (int t = 0; t < GZ; ++t)
            cdsum += g_tasksum[t] / (float)g_cnt[t >> 1];
        float l1num = wl[0] + wl[1] + wl[2] + wl[3];
        int msum = 0;
#pragma unroll
        for (int bb = 0; bb < BB; ++bb) msum += g_cnt[bb];
        float l1 = l1num / 3.0f / (float)msum;
        float cd = cdsum / (float)BB;
        out[0] = l1 + expf(-l1) * cd;
        g_done = 0;                        // reset for next graph replay
    }
    __syncthreads();
    if (tid < BB)  g_cnt[tid] = 0;
    if (tid < GZ)  g_done_task[tid] = 0;
}

// ---------------------------------------------------------------------------
extern "C" void kernel_launch(void* const* d_in, const int* in_sizes, int n_in,
                              void* d_out, int out_size) {
    const float* pred   = (const float*)d_in[0];
    const float* target = (const float*)d_in[1];
    const int*   mask   = (const int*)  d_in[2];
    const float* points = (const float*)d_in[3];
    float* out = (float*)d_out;

    prep_kernel<<<128, 128>>>(pred, target, mask, points);

    dim3 grid(GQ, RSPLIT, GZ);   // (4, 32, 16) = 2048 blocks, all live
    chamfer_kernel<<<grid, TB>>>(out);
}